// round 3
// baseline (speedup 1.0000x reference)
#include <cuda_runtime.h>
#include <cuda_bf16.h>
#include <math.h>

// Problem constants
#define T_ 2048
#define B_ 2
#define D_ 768
#define H_ 8
#define HD_ 96
#define FFN_ 3072
#define NR_ (T_ * B_)          // 4096 rows
#define BH_ (B_ * H_)          // 16 attention batches

// ---------------- scratch (__device__ globals; no allocation allowed) ----------------
__device__ float g_q[NR_ * D_];
__device__ float g_k[NR_ * D_];
__device__ float g_v[NR_ * D_];
__device__ float g_scores[(long)BH_ * T_ * T_];   // 268 MB
__device__ float g_attn[NR_ * D_];
__device__ float g_tmp1[NR_ * D_];
__device__ float g_x1[NR_ * D_];
__device__ float g_h1[NR_ * FFN_];
__device__ float g_y[NR_ * D_];

// ---------------- 128x128 tiled GEMM, 8x8 microtile, double-buffered ----------------
// C[M,N] = alpha * A[M,K] @ op(B) + bias + relu + residual
// TRANS_B=true : B is [N,K] row-major -> C = A @ B^T   (assumes N % 128 == 0, no guards)
// TRANS_B=false: B is [K,N] row-major -> C = A @ B     (N guarded; N % 4 == 0)
// Assumes: M % 128 == 0, K % 16 == 0, all pointers/leading dims 16B-aligned.
// Batched via blockIdx.z -> (zb, zh) with strided pointer offsets.
template<bool TRANS_B>
__global__ __launch_bounds__(256, 2)
void gemm128(const float* __restrict__ A,
             const float* __restrict__ Bm,
             const float* __restrict__ bias,
             const float* __restrict__ residual,
             float* __restrict__ C,
             int M, int N, int K,
             int lda, int ldb, int ldc,
             long offA1, long offA2,
             long offB1, long offB2,
             long offC1, long offC2,
             int Hh, float alpha, int relu)
{
    __shared__ float As[2][16][132];
    __shared__ float Bs[2][16][132];

    const int z = blockIdx.z;
    const int zb = z / Hh, zh = z - zb * Hh;
    A  += (long)zb * offA1 + (long)zh * offA2;
    Bm += (long)zb * offB1 + (long)zh * offB2;
    C  += (long)zb * offC1 + (long)zh * offC2;
    const float* R = residual ? residual + (long)zb * offC1 + (long)zh * offC2
                              : (const float*)0;

    const int tid = threadIdx.x;
    const int tx = tid & 15;        // 0..15
    const int ty = tid >> 4;        // 0..15
    const int rowBase = blockIdx.y * 128;
    const int colBase = blockIdx.x * 128;

    // A / trans-B loader mapping: 128 rows x 16 k, 8 floats per thread
    const int aRow = tid >> 1;            // 0..127
    const int aK   = (tid & 1) * 4;       // 0 or 4; chunks at aK and aK+8
    // no-trans-B loader mapping: 16 k-rows x 128 n, 8 floats per thread
    const int kRow = tid >> 4;            // 0..15
    const int nq   = (tid & 15) * 8;      // 0..120

    float4 ra0, ra1, rb0, rb1;

    auto ldg = [&](int k0) {
        {
            const float* p = A + (long)(rowBase + aRow) * lda + k0 + aK;
            ra0 = *(const float4*)p;
            ra1 = *(const float4*)(p + 8);
        }
        if (TRANS_B) {
            const float* p = Bm + (long)(colBase + aRow) * ldb + k0 + aK;
            rb0 = *(const float4*)p;
            rb1 = *(const float4*)(p + 8);
        } else {
            const int gn = colBase + nq;
            const float* p = Bm + (long)(k0 + kRow) * ldb + gn;
            rb0 = (gn     < N) ? *(const float4*)p       : make_float4(0.f,0.f,0.f,0.f);
            rb1 = (gn + 4 < N) ? *(const float4*)(p + 4) : make_float4(0.f,0.f,0.f,0.f);
        }
    };

    auto sts = [&](int buf) {
        float* as = &As[buf][0][0];
        float* bs = &Bs[buf][0][0];
        as[(aK + 0) * 132 + aRow] = ra0.x;
        as[(aK + 1) * 132 + aRow] = ra0.y;
        as[(aK + 2) * 132 + aRow] = ra0.z;
        as[(aK + 3) * 132 + aRow] = ra0.w;
        as[(aK + 8) * 132 + aRow] = ra1.x;
        as[(aK + 9) * 132 + aRow] = ra1.y;
        as[(aK +10) * 132 + aRow] = ra1.z;
        as[(aK +11) * 132 + aRow] = ra1.w;
        if (TRANS_B) {
            bs[(aK + 0) * 132 + aRow] = rb0.x;
            bs[(aK + 1) * 132 + aRow] = rb0.y;
            bs[(aK + 2) * 132 + aRow] = rb0.z;
            bs[(aK + 3) * 132 + aRow] = rb0.w;
            bs[(aK + 8) * 132 + aRow] = rb1.x;
            bs[(aK + 9) * 132 + aRow] = rb1.y;
            bs[(aK +10) * 132 + aRow] = rb1.z;
            bs[(aK +11) * 132 + aRow] = rb1.w;
        } else {
            *(float4*)&bs[kRow * 132 + nq]     = rb0;
            *(float4*)&bs[kRow * 132 + nq + 4] = rb1;
        }
    };

    float acc[8][8];
#pragma unroll
    for (int i = 0; i < 8; i++)
#pragma unroll
        for (int j = 0; j < 8; j++) acc[i][j] = 0.f;

    // prologue
    ldg(0);
    sts(0);
    __syncthreads();

    int buf = 0;
    for (int k0 = 0; ;) {
        const int knext = k0 + 16;
        const bool has = knext < K;
        if (has) ldg(knext);

        // compute on As[buf]/Bs[buf]
#pragma unroll
        for (int kk = 0; kk < 16; kk++) {
            const float* as = &As[buf][kk][0];
            const float* bs = &Bs[buf][kk][0];
            float4 a0 = *(const float4*)&as[ty * 4];
            float4 a1 = *(const float4*)&as[64 + ty * 4];
            float4 b0 = *(const float4*)&bs[tx * 4];
            float4 b1 = *(const float4*)&bs[64 + tx * 4];
            float a[8] = {a0.x,a0.y,a0.z,a0.w,a1.x,a1.y,a1.z,a1.w};
            float b[8] = {b0.x,b0.y,b0.z,b0.w,b1.x,b1.y,b1.z,b1.w};
#pragma unroll
            for (int i = 0; i < 8; i++)
#pragma unroll
                for (int j = 0; j < 8; j++)
                    acc[i][j] += a[i] * b[j];
        }

        if (!has) break;
        sts(buf ^ 1);
        __syncthreads();
        buf ^= 1;
        k0 = knext;
    }

    // ---- epilogue
    int rows[8], cols[8];
#pragma unroll
    for (int i = 0; i < 4; i++) {
        rows[i]     = rowBase + ty * 4 + i;
        rows[i + 4] = rowBase + 64 + ty * 4 + i;
        cols[i]     = colBase + tx * 4 + i;
        cols[i + 4] = colBase + 64 + tx * 4 + i;
    }
    float bv[8];
#pragma unroll
    for (int j = 0; j < 8; j++)
        bv[j] = (bias && cols[j] < N) ? bias[cols[j]] : 0.f;

#pragma unroll
    for (int i = 0; i < 8; i++) {
        const long rowOff = (long)rows[i] * ldc;
#pragma unroll
        for (int j = 0; j < 8; j++) {
            if (cols[j] < N) {
                float v = acc[i][j] * alpha + bv[j];
                if (relu) v = fmaxf(v, 0.f);
                if (R) v += R[rowOff + cols[j]];
                C[rowOff + cols[j]] = v;
            }
        }
    }
}

// ---------------- block reductions ----------------
__device__ __forceinline__ float blockReduceSum(float v) {
    __shared__ float s[8];
#pragma unroll
    for (int o = 16; o > 0; o >>= 1) v += __shfl_xor_sync(0xffffffffu, v, o);
    int w = threadIdx.x >> 5, l = threadIdx.x & 31;
    if (l == 0) s[w] = v;
    __syncthreads();
    if (threadIdx.x < 32) {
        v = (threadIdx.x < 8) ? s[threadIdx.x] : 0.f;
#pragma unroll
        for (int o = 4; o > 0; o >>= 1) v += __shfl_xor_sync(0xffffffffu, v, o);
        if (threadIdx.x == 0) s[0] = v;
    }
    __syncthreads();
    v = s[0];
    __syncthreads();
    return v;
}

__device__ __forceinline__ float blockReduceMax(float v) {
    __shared__ float s[8];
#pragma unroll
    for (int o = 16; o > 0; o >>= 1) v = fmaxf(v, __shfl_xor_sync(0xffffffffu, v, o));
    int w = threadIdx.x >> 5, l = threadIdx.x & 31;
    if (l == 0) s[w] = v;
    __syncthreads();
    if (threadIdx.x < 32) {
        v = (threadIdx.x < 8) ? s[threadIdx.x] : -1e30f;
#pragma unroll
        for (int o = 4; o > 0; o >>= 1) v = fmaxf(v, __shfl_xor_sync(0xffffffffu, v, o));
        if (threadIdx.x == 0) s[0] = v;
    }
    __syncthreads();
    v = s[0];
    __syncthreads();
    return v;
}

// ---------------- softmax over rows of length 2048 (256 thr, float4) ----------------
__global__ void softmax_kernel(float* __restrict__ S) {
    long row = blockIdx.x;
    float4* p = (float4*)(S + row * T_);
    int tid = threadIdx.x;
    float4 v0 = p[tid];
    float4 v1 = p[tid + 256];
    float m = fmaxf(fmaxf(fmaxf(v0.x, v0.y), fmaxf(v0.z, v0.w)),
                    fmaxf(fmaxf(v1.x, v1.y), fmaxf(v1.z, v1.w)));
    m = blockReduceMax(m);
    v0.x = __expf(v0.x - m); v0.y = __expf(v0.y - m);
    v0.z = __expf(v0.z - m); v0.w = __expf(v0.w - m);
    v1.x = __expf(v1.x - m); v1.y = __expf(v1.y - m);
    v1.z = __expf(v1.z - m); v1.w = __expf(v1.w - m);
    float sum = v0.x + v0.y + v0.z + v0.w + v1.x + v1.y + v1.z + v1.w;
    sum = blockReduceSum(sum);
    float inv = 1.f / sum;
    v0.x *= inv; v0.y *= inv; v0.z *= inv; v0.w *= inv;
    v1.x *= inv; v1.y *= inv; v1.z *= inv; v1.w *= inv;
    p[tid] = v0;
    p[tid + 256] = v1;
}

// ---------------- layernorm over rows of length 768 (256 thr, 3/thread) ----------------
__global__ void layernorm_kernel(const float* __restrict__ X,
                                 const float* __restrict__ g,
                                 const float* __restrict__ b,
                                 float* __restrict__ Y) {
    long row = blockIdx.x;
    const float* p = X + row * D_;
    float* q = Y + row * D_;
    int tid = threadIdx.x;
    float vals[3];
    float sum = 0.f;
#pragma unroll
    for (int i = 0; i < 3; i++) {
        vals[i] = p[tid + i * 256];
        sum += vals[i];
    }
    float mu = blockReduceSum(sum) * (1.f / D_);
    float vs = 0.f;
#pragma unroll
    for (int i = 0; i < 3; i++) {
        float d = vals[i] - mu;
        vs += d * d;
    }
    float var = blockReduceSum(vs) * (1.f / D_);
    float rs = rsqrtf(var + 1e-5f);
#pragma unroll
    for (int i = 0; i < 3; i++) {
        int c = tid + i * 256;
        q[c] = (vals[i] - mu) * rs * g[c] + b[c];
    }
}

// ---------------- launch ----------------
extern "C" void kernel_launch(void* const* d_in, const int* in_sizes, int n_in,
                              void* d_out, int out_size)
{
    const float* x     = (const float*)d_in[0];
    const float* wq    = (const float*)d_in[1];
    const float* bq    = (const float*)d_in[2];
    const float* wk    = (const float*)d_in[3];
    const float* bk    = (const float*)d_in[4];
    const float* wv    = (const float*)d_in[5];
    const float* bv    = (const float*)d_in[6];
    const float* wo    = (const float*)d_in[7];
    const float* bo    = (const float*)d_in[8];
    const float* ln1g  = (const float*)d_in[9];
    const float* ln1b  = (const float*)d_in[10];
    const float* w1    = (const float*)d_in[11];
    const float* b1    = (const float*)d_in[12];
    const float* w2    = (const float*)d_in[13];
    const float* b2    = (const float*)d_in[14];
    const float* ln2g  = (const float*)d_in[15];
    const float* ln2b  = (const float*)d_in[16];
    float* out = (float*)d_out;

    float *q, *k, *v, *sc, *attn, *tmp1, *x1, *h1, *y;
    cudaGetSymbolAddress((void**)&q,    g_q);
    cudaGetSymbolAddress((void**)&k,    g_k);
    cudaGetSymbolAddress((void**)&v,    g_v);
    cudaGetSymbolAddress((void**)&sc,   g_scores);
    cudaGetSymbolAddress((void**)&attn, g_attn);
    cudaGetSymbolAddress((void**)&tmp1, g_tmp1);
    cudaGetSymbolAddress((void**)&x1,   g_x1);
    cudaGetSymbolAddress((void**)&h1,   g_h1);
    cudaGetSymbolAddress((void**)&y,    g_y);

    const float scale = 0.102062072615966f;  // 1/sqrt(96)
    dim3 blk(256);

    // QKV projections: [4096,768] = x @ W^T + b
    dim3 gProj(D_ / 128, NR_ / 128, 1);
    gemm128<true><<<gProj, blk>>>(x, wq, bq, nullptr, q, NR_, D_, D_,
                                  D_, D_, D_, 0,0,0,0,0,0, 1, 1.f, 0);
    gemm128<true><<<gProj, blk>>>(x, wk, bk, nullptr, k, NR_, D_, D_,
                                  D_, D_, D_, 0,0,0,0,0,0, 1, 1.f, 0);
    gemm128<true><<<gProj, blk>>>(x, wv, bv, nullptr, v, NR_, D_, D_,
                                  D_, D_, D_, 0,0,0,0,0,0, 1, 1.f, 0);

    // scores[z=b*H+h][t][s] = scale * Q_bh @ K_bh^T   (batched, strided views)
    dim3 gScore(T_ / 128, T_ / 128, BH_);
    gemm128<true><<<gScore, blk>>>(q, k, nullptr, nullptr, sc,
                                   T_, T_, HD_,
                                   B_ * D_, B_ * D_, T_,
                                   (long)D_, (long)HD_,
                                   (long)D_, (long)HD_,
                                   (long)H_ * T_ * T_, (long)T_ * T_,
                                   H_, scale, 0);

    // softmax over s
    softmax_kernel<<<(unsigned)((long)BH_ * T_), blk>>>(sc);

    // attn = P @ V (batched; B in [K,N] layout via strided view of v)
    dim3 gPV(1, T_ / 128, BH_);
    gemm128<false><<<gPV, blk>>>(sc, v, nullptr, nullptr, attn,
                                 T_, HD_, T_,
                                 T_, B_ * D_, B_ * D_,
                                 (long)H_ * T_ * T_, (long)T_ * T_,
                                 (long)D_, (long)HD_,
                                 (long)D_, (long)HD_,
                                 H_, 1.f, 0);

    // O projection + residual(x)
    gemm128<true><<<gProj, blk>>>(attn, wo, bo, x, tmp1, NR_, D_, D_,
                                  D_, D_, D_, 0,0,0,0,0,0, 1, 1.f, 0);

    // LN1
    layernorm_kernel<<<NR_, blk>>>(tmp1, ln1g, ln1b, x1);

    // FFN1: relu(x1 @ w1^T + b1)
    dim3 gF1(FFN_ / 128, NR_ / 128, 1);
    gemm128<true><<<gF1, blk>>>(x1, w1, b1, nullptr, h1, NR_, FFN_, D_,
                                D_, D_, FFN_, 0,0,0,0,0,0, 1, 1.f, 1);

    // FFN2: h1 @ w2^T + b2 + x1
    gemm128<true><<<gProj, blk>>>(h1, w2, b2, x1, y, NR_, D_, FFN_,
                                  FFN_, FFN_, D_, 0,0,0,0,0,0, 1, 1.f, 0);

    // LN2 -> output
    layernorm_kernel<<<NR_, blk>>>(y, ln2g, ln2b, out);
}

// round 5
// speedup vs baseline: 2.5280x; 2.5280x over previous
#include <cuda_runtime.h>
#include <cuda_bf16.h>
#include <math.h>
#include <stdint.h>

// Problem constants
#define T_ 2048
#define B_ 2
#define D_ 768
#define H_ 8
#define HD_ 96
#define FFN_ 3072
#define NR_ (T_ * B_)          // 4096 rows
#define BH_ (B_ * H_)          // 16 attention batches

// ---------------- scratch (__device__ globals; no allocation allowed) ----------------
__device__ float g_q[NR_ * D_];
__device__ float g_k[NR_ * D_];
__device__ float g_v[NR_ * D_];
__device__ float g_scores[(long)BH_ * T_ * T_];   // 268 MB
__device__ float g_attn[NR_ * D_];
__device__ float g_tmp1[NR_ * D_];
__device__ float g_x1[NR_ * D_];
__device__ float g_h1[NR_ * FFN_];
__device__ float g_y[NR_ * D_];

// ================= helpers =================
__device__ __forceinline__ uint32_t pack2(__nv_bfloat16 a, __nv_bfloat16 b) {
    return (uint32_t)__bfloat16_as_ushort(a) | ((uint32_t)__bfloat16_as_ushort(b) << 16);
}
__device__ __forceinline__ void split2(float v, __nv_bfloat16& h, __nv_bfloat16& l) {
    h = __float2bfloat16(v);
    l = __float2bfloat16(v - __bfloat162float(h));
}
__device__ __forceinline__ void mma16816(float* c, const uint32_t* a, const uint32_t* b) {
    asm volatile(
        "mma.sync.aligned.m16n8k16.row.col.f32.bf16.bf16.f32 "
        "{%0,%1,%2,%3}, {%4,%5,%6,%7}, {%8,%9}, {%0,%1,%2,%3};"
        : "+f"(c[0]), "+f"(c[1]), "+f"(c[2]), "+f"(c[3])
        : "r"(a[0]), "r"(a[1]), "r"(a[2]), "r"(a[3]), "r"(b[0]), "r"(b[1]));
}

// ================= HMMA split-bf16 GEMM =================
// C[M,N] = alpha * A[M,K] @ op(B) + bias (+relu) (+residual)
// Internally: A,B tiles are split fp32 -> (hi,lo) bf16 in smem; accumulate
//   Ah*Bh + Ah*Bl + Al*Bh in fp32 via mma.sync (error ~2^-16, well under 1e-3).
// TRANS_B=true : B is [N,K] row-major -> C = A @ B^T
// TRANS_B=false: B is [K,N] row-major -> C = A @ B   (N guarded, N%4==0)
// Assumes M%128==0, K%32==0, K>=64; TRANS_B requires N%128==0.
// Batched via blockIdx.z -> (zb, zh) with strided pointer offsets.
#define KC 32
#define PA 40                          // bf16 element pitch (80 B/row, conflict-free frags)
#define TILE_E (128 * PA)              // elements per tile
#define GEMM_SMEM (2 * 4 * TILE_E * 2) // 2 bufs x (Ah,Al,Bh,Bl) x bytes = 81920

template<bool TRANS_B>
__global__ __launch_bounds__(256)
void gemm_hmma(const float* __restrict__ A,
               const float* __restrict__ Bm,
               const float* __restrict__ bias,
               const float* __restrict__ residual,
               float* __restrict__ C,
               int M, int N, int K,
               int lda, int ldb, int ldc,
               long offA1, long offA2,
               long offB1, long offB2,
               long offC1, long offC2,
               int Hh, float alpha, int relu)
{
    extern __shared__ char dsm[];
    __nv_bfloat16* sm = (__nv_bfloat16*)dsm;

    const int z = blockIdx.z;
    const int zb = z / Hh, zh = z - zb * Hh;
    A  += (long)zb * offA1 + (long)zh * offA2;
    Bm += (long)zb * offB1 + (long)zh * offB2;
    C  += (long)zb * offC1 + (long)zh * offC2;
    const float* R = residual ? residual + (long)zb * offC1 + (long)zh * offC2
                              : (const float*)0;

    const int tid = threadIdx.x;
    const int lane = tid & 31;
    const int wid = tid >> 5;
    const int warpM = wid >> 2;        // 0..1 -> 64-row half
    const int warpN = wid & 3;         // 0..3 -> 32-col quarter
    const int rowBase = blockIdx.y * 128;
    const int colBase = blockIdx.x * 128;

    // ---- staging registers for global loads
    float4 stA[4];
    float4 stB[4];

    // A fill mapping: idx over 128 rows x 8 k-chunks(4 floats)
    auto ldA = [&](int k0) {
#pragma unroll
        for (int t = 0; t < 4; t++) {
            const int idx = (t << 8) + tid;
            const int r = idx >> 3, kq = (idx & 7) << 2;
            stA[t] = *(const float4*)(A + (long)(rowBase + r) * lda + k0 + kq);
        }
    };
    auto ldB = [&](int k0) {
        if (TRANS_B) {
#pragma unroll
            for (int t = 0; t < 4; t++) {
                const int idx = (t << 8) + tid;
                const int r = idx >> 3, kq = (idx & 7) << 2;
                stB[t] = *(const float4*)(Bm + (long)(colBase + r) * ldb + k0 + kq);
            }
        } else {
#pragma unroll
            for (int t = 0; t < 4; t++) {
                const int idx = (t << 8) + tid;
                const int kk = idx >> 5, nq = (idx & 31) << 2;
                const int gn = colBase + nq;
                stB[t] = (gn < N) ? *(const float4*)(Bm + (long)(k0 + kk) * ldb + gn)
                                  : make_float4(0.f, 0.f, 0.f, 0.f);
            }
        }
    };
    auto stS = [&](int buf) {
        __nv_bfloat16* pAh = sm + buf * 4 * TILE_E;
        __nv_bfloat16* pAl = pAh + TILE_E;
        __nv_bfloat16* pBh = pAh + 2 * TILE_E;
        __nv_bfloat16* pBl = pAh + 3 * TILE_E;
#pragma unroll
        for (int t = 0; t < 4; t++) {
            const int idx = (t << 8) + tid;
            const int r = idx >> 3, kq = (idx & 7) << 2;
            __nv_bfloat16 h0,h1,h2,h3,l0,l1,l2,l3;
            split2(stA[t].x,h0,l0); split2(stA[t].y,h1,l1);
            split2(stA[t].z,h2,l2); split2(stA[t].w,h3,l3);
            *(uint2*)&pAh[r * PA + kq] = make_uint2(pack2(h0,h1), pack2(h2,h3));
            *(uint2*)&pAl[r * PA + kq] = make_uint2(pack2(l0,l1), pack2(l2,l3));
        }
        if (TRANS_B) {
#pragma unroll
            for (int t = 0; t < 4; t++) {
                const int idx = (t << 8) + tid;
                const int r = idx >> 3, kq = (idx & 7) << 2;
                __nv_bfloat16 h0,h1,h2,h3,l0,l1,l2,l3;
                split2(stB[t].x,h0,l0); split2(stB[t].y,h1,l1);
                split2(stB[t].z,h2,l2); split2(stB[t].w,h3,l3);
                *(uint2*)&pBh[r * PA + kq] = make_uint2(pack2(h0,h1), pack2(h2,h3));
                *(uint2*)&pBl[r * PA + kq] = make_uint2(pack2(l0,l1), pack2(l2,l3));
            }
        } else {
#pragma unroll
            for (int t = 0; t < 4; t++) {
                const int idx = (t << 8) + tid;
                const int kk = idx >> 5, nq = (idx & 31) << 2;
                const float vv[4] = {stB[t].x, stB[t].y, stB[t].z, stB[t].w};
#pragma unroll
                for (int j = 0; j < 4; j++) {
                    __nv_bfloat16 h, l;
                    split2(vv[j], h, l);
                    pBh[(nq + j) * PA + kk] = h;
                    pBl[(nq + j) * PA + kk] = l;
                }
            }
        }
    };

    float acc[4][4][4];
#pragma unroll
    for (int i = 0; i < 4; i++)
#pragma unroll
        for (int j = 0; j < 4; j++)
#pragma unroll
            for (int r = 0; r < 4; r++) acc[i][j][r] = 0.f;

    const int NC = K / KC;
    ldA(0); ldB(0);
    stS(0);
    __syncthreads();

    int buf = 0;
    for (int c = 0; c < NC; c++) {
        const bool has = (c + 1) < NC;
        if (has) { ldA((c + 1) * KC); ldB((c + 1) * KC); }

        const __nv_bfloat16* pAh = sm + buf * 4 * TILE_E;
        const __nv_bfloat16* pAl = pAh + TILE_E;
        const __nv_bfloat16* pBh = pAh + 2 * TILE_E;
        const __nv_bfloat16* pBl = pAh + 3 * TILE_E;
        const int rql = lane >> 2;
        const int kof = (lane & 3) << 1;

#pragma unroll
        for (int ks = 0; ks < KC; ks += 16) {
            const int kcol = ks + kof;
            uint32_t bh[4][2], bl[4][2];
#pragma unroll
            for (int nt = 0; nt < 4; nt++) {
                const int n0 = warpN * 32 + nt * 8 + rql;
                bh[nt][0] = *(const uint32_t*)&pBh[n0 * PA + kcol];
                bh[nt][1] = *(const uint32_t*)&pBh[n0 * PA + kcol + 8];
                bl[nt][0] = *(const uint32_t*)&pBl[n0 * PA + kcol];
                bl[nt][1] = *(const uint32_t*)&pBl[n0 * PA + kcol + 8];
            }
#pragma unroll
            for (int mt = 0; mt < 4; mt++) {
                const int r0 = warpM * 64 + mt * 16 + rql;
                uint32_t ah[4], al[4];
                ah[0] = *(const uint32_t*)&pAh[r0 * PA + kcol];
                ah[1] = *(const uint32_t*)&pAh[(r0 + 8) * PA + kcol];
                ah[2] = *(const uint32_t*)&pAh[r0 * PA + kcol + 8];
                ah[3] = *(const uint32_t*)&pAh[(r0 + 8) * PA + kcol + 8];
                al[0] = *(const uint32_t*)&pAl[r0 * PA + kcol];
                al[1] = *(const uint32_t*)&pAl[(r0 + 8) * PA + kcol];
                al[2] = *(const uint32_t*)&pAl[r0 * PA + kcol + 8];
                al[3] = *(const uint32_t*)&pAl[(r0 + 8) * PA + kcol + 8];
#pragma unroll
                for (int nt = 0; nt < 4; nt++) {
                    mma16816(acc[mt][nt], ah, bh[nt]);
                    mma16816(acc[mt][nt], ah, bl[nt]);
                    mma16816(acc[mt][nt], al, bh[nt]);
                }
            }
        }

        if (has) stS(buf ^ 1);
        __syncthreads();
        buf ^= 1;
    }

    // ---- epilogue: c frag: rows r,(r+8); cols cb,cb+1
    const int rql = lane >> 2;
    const int cof = (lane & 3) << 1;
#pragma unroll
    for (int mt = 0; mt < 4; mt++) {
        const int r0 = rowBase + warpM * 64 + mt * 16 + rql;
#pragma unroll
        for (int nt = 0; nt < 4; nt++) {
            const int cb = colBase + warpN * 32 + nt * 8 + cof;
            if (cb >= N) continue;
            float* a4 = acc[mt][nt];
            float2 bb = make_float2(0.f, 0.f);
            if (bias) bb = *(const float2*)(bias + cb);
            float v0 = a4[0] * alpha + bb.x;
            float v1 = a4[1] * alpha + bb.y;
            float v2 = a4[2] * alpha + bb.x;
            float v3 = a4[3] * alpha + bb.y;
            if (relu) {
                v0 = fmaxf(v0, 0.f); v1 = fmaxf(v1, 0.f);
                v2 = fmaxf(v2, 0.f); v3 = fmaxf(v3, 0.f);
            }
            const long o0 = (long)r0 * ldc + cb;
            const long o1 = (long)(r0 + 8) * ldc + cb;
            if (R) {
                float2 r00 = *(const float2*)(R + o0);
                float2 r11 = *(const float2*)(R + o1);
                v0 += r00.x; v1 += r00.y; v2 += r11.x; v3 += r11.y;
            }
            *(float2*)(C + o0) = make_float2(v0, v1);
            *(float2*)(C + o1) = make_float2(v2, v3);
        }
    }
}

// ---------------- block reductions ----------------
__device__ __forceinline__ float blockReduceSum(float v) {
    __shared__ float s[8];
#pragma unroll
    for (int o = 16; o > 0; o >>= 1) v += __shfl_xor_sync(0xffffffffu, v, o);
    int w = threadIdx.x >> 5, l = threadIdx.x & 31;
    if (l == 0) s[w] = v;
    __syncthreads();
    if (threadIdx.x < 32) {
        v = (threadIdx.x < 8) ? s[threadIdx.x] : 0.f;
#pragma unroll
        for (int o = 4; o > 0; o >>= 1) v += __shfl_xor_sync(0xffffffffu, v, o);
        if (threadIdx.x == 0) s[0] = v;
    }
    __syncthreads();
    v = s[0];
    __syncthreads();
    return v;
}
__device__ __forceinline__ float blockReduceMax(float v) {
    __shared__ float s[8];
#pragma unroll
    for (int o = 16; o > 0; o >>= 1) v = fmaxf(v, __shfl_xor_sync(0xffffffffu, v, o));
    int w = threadIdx.x >> 5, l = threadIdx.x & 31;
    if (l == 0) s[w] = v;
    __syncthreads();
    if (threadIdx.x < 32) {
        v = (threadIdx.x < 8) ? s[threadIdx.x] : -1e30f;
#pragma unroll
        for (int o = 4; o > 0; o >>= 1) v = fmaxf(v, __shfl_xor_sync(0xffffffffu, v, o));
        if (threadIdx.x == 0) s[0] = v;
    }
    __syncthreads();
    v = s[0];
    __syncthreads();
    return v;
}

// ---------------- softmax over rows of length 2048 ----------------
__global__ void softmax_kernel(float* __restrict__ S) {
    long row = blockIdx.x;
    float4* p = (float4*)(S + row * T_);
    int tid = threadIdx.x;
    float4 v0 = p[tid];
    float4 v1 = p[tid + 256];
    float m = fmaxf(fmaxf(fmaxf(v0.x, v0.y), fmaxf(v0.z, v0.w)),
                    fmaxf(fmaxf(v1.x, v1.y), fmaxf(v1.z, v1.w)));
    m = blockReduceMax(m);
    v0.x = __expf(v0.x - m); v0.y = __expf(v0.y - m);
    v0.z = __expf(v0.z - m); v0.w = __expf(v0.w - m);
    v1.x = __expf(v1.x - m); v1.y = __expf(v1.y - m);
    v1.z = __expf(v1.z - m); v1.w = __expf(v1.w - m);
    float sum = v0.x + v0.y + v0.z + v0.w + v1.x + v1.y + v1.z + v1.w;
    sum = blockReduceSum(sum);
    float inv = 1.f / sum;
    v0.x *= inv; v0.y *= inv; v0.z *= inv; v0.w *= inv;
    v1.x *= inv; v1.y *= inv; v1.z *= inv; v1.w *= inv;
    p[tid] = v0;
    p[tid + 256] = v1;
}

// ---------------- layernorm over rows of length 768 ----------------
__global__ void layernorm_kernel(const float* __restrict__ X,
                                 const float* __restrict__ g,
                                 const float* __restrict__ b,
                                 float* __restrict__ Y) {
    long row = blockIdx.x;
    const float* p = X + row * D_;
    float* q = Y + row * D_;
    int tid = threadIdx.x;
    float vals[3];
    float sum = 0.f;
#pragma unroll
    for (int i = 0; i < 3; i++) {
        vals[i] = p[tid + i * 256];
        sum += vals[i];
    }
    float mu = blockReduceSum(sum) * (1.f / D_);
    float vs = 0.f;
#pragma unroll
    for (int i = 0; i < 3; i++) {
        float d = vals[i] - mu;
        vs += d * d;
    }
    float var = blockReduceSum(vs) * (1.f / D_);
    float rs = rsqrtf(var + 1e-5f);
#pragma unroll
    for (int i = 0; i < 3; i++) {
        int c = tid + i * 256;
        q[c] = (vals[i] - mu) * rs * g[c] + b[c];
    }
}

// ---------------- launch ----------------
extern "C" void kernel_launch(void* const* d_in, const int* in_sizes, int n_in,
                              void* d_out, int out_size)
{
    const float* x     = (const float*)d_in[0];
    const float* wq    = (const float*)d_in[1];
    const float* bq    = (const float*)d_in[2];
    const float* wk    = (const float*)d_in[3];
    const float* bk    = (const float*)d_in[4];
    const float* wv    = (const float*)d_in[5];
    const float* bv    = (const float*)d_in[6];
    const float* wo    = (const float*)d_in[7];
    const float* bo    = (const float*)d_in[8];
    const float* ln1g  = (const float*)d_in[9];
    const float* ln1b  = (const float*)d_in[10];
    const float* w1    = (const float*)d_in[11];
    const float* b1    = (const float*)d_in[12];
    const float* w2    = (const float*)d_in[13];
    const float* b2    = (const float*)d_in[14];
    const float* ln2g  = (const float*)d_in[15];
    const float* ln2b  = (const float*)d_in[16];
    float* out = (float*)d_out;

    float *q, *k, *v, *sc, *attn, *tmp1, *x1, *h1, *y;
    cudaGetSymbolAddress((void**)&q,    g_q);
    cudaGetSymbolAddress((void**)&k,    g_k);
    cudaGetSymbolAddress((void**)&v,    g_v);
    cudaGetSymbolAddress((void**)&sc,   g_scores);
    cudaGetSymbolAddress((void**)&attn, g_attn);
    cudaGetSymbolAddress((void**)&tmp1, g_tmp1);
    cudaGetSymbolAddress((void**)&x1,   g_x1);
    cudaGetSymbolAddress((void**)&h1,   g_h1);
    cudaGetSymbolAddress((void**)&y,    g_y);

    cudaFuncSetAttribute(gemm_hmma<true>,  cudaFuncAttributeMaxDynamicSharedMemorySize, GEMM_SMEM);
    cudaFuncSetAttribute(gemm_hmma<false>, cudaFuncAttributeMaxDynamicSharedMemorySize, GEMM_SMEM);

    const float scale = 0.102062072615966f;  // 1/sqrt(96)
    dim3 blk(256);

    // QKV projections: [4096,768] = x @ W^T + b
    dim3 gProj(D_ / 128, NR_ / 128, 1);
    gemm_hmma<true><<<gProj, blk, GEMM_SMEM>>>(x, wq, bq, nullptr, q, NR_, D_, D_,
                                               D_, D_, D_, 0,0,0,0,0,0, 1, 1.f, 0);
    gemm_hmma<true><<<gProj, blk, GEMM_SMEM>>>(x, wk, bk, nullptr, k, NR_, D_, D_,
                                               D_, D_, D_, 0,0,0,0,0,0, 1, 1.f, 0);
    gemm_hmma<true><<<gProj, blk, GEMM_SMEM>>>(x, wv, bv, nullptr, v, NR_, D_, D_,
                                               D_, D_, D_, 0,0,0,0,0,0, 1, 1.f, 0);

    // scores = scale * Q_bh @ K_bh^T   (batched strided views; K=96)
    dim3 gScore(T_ / 128, T_ / 128, BH_);
    gemm_hmma<true><<<gScore, blk, GEMM_SMEM>>>(q, k, nullptr, nullptr, sc,
                                                T_, T_, HD_,
                                                B_ * D_, B_ * D_, T_,
                                                (long)D_, (long)HD_,
                                                (long)D_, (long)HD_,
                                                (long)H_ * T_ * T_, (long)T_ * T_,
                                                H_, scale, 0);

    softmax_kernel<<<(unsigned)((long)BH_ * T_), blk>>>(sc);

    // attn = P @ V (batched; B in [K,N] layout via strided view of v)
    dim3 gPV(1, T_ / 128, BH_);
    gemm_hmma<false><<<gPV, blk, GEMM_SMEM>>>(sc, v, nullptr, nullptr, attn,
                                              T_, HD_, T_,
                                              T_, B_ * D_, B_ * D_,
                                              (long)H_ * T_ * T_, (long)T_ * T_,
                                              (long)D_, (long)HD_,
                                              (long)D_, (long)HD_,
                                              H_, 1.f, 0);

    // O projection + residual(x)
    gemm_hmma<true><<<gProj, blk, GEMM_SMEM>>>(attn, wo, bo, x, tmp1, NR_, D_, D_,
                                               D_, D_, D_, 0,0,0,0,0,0, 1, 1.f, 0);

    layernorm_kernel<<<NR_, blk>>>(tmp1, ln1g, ln1b, x1);

    // FFN1: relu(x1 @ w1^T + b1)
    dim3 gF1(FFN_ / 128, NR_ / 128, 1);
    gemm_hmma<true><<<gF1, blk, GEMM_SMEM>>>(x1, w1, b1, nullptr, h1, NR_, FFN_, D_,
                                             D_, D_, FFN_, 0,0,0,0,0,0, 1, 1.f, 1);

    // FFN2: h1 @ w2^T + b2 + x1
    gemm_hmma<true><<<gProj, blk, GEMM_SMEM>>>(h1, w2, b2, x1, y, NR_, D_, FFN_,
                                               FFN_, FFN_, D_, 0,0,0,0,0,0, 1, 1.f, 0);

    layernorm_kernel<<<NR_, blk>>>(y, ln2g, ln2b, out);
}

// round 7
// speedup vs baseline: 3.2258x; 1.2760x over previous
#include <cuda_runtime.h>
#include <cuda_bf16.h>
#include <math.h>
#include <stdint.h>

// Problem constants
#define T_ 2048
#define B_ 2
#define D_ 768
#define H_ 8
#define HD_ 96
#define FFN_ 3072
#define NR_ (T_ * B_)          // 4096 rows
#define BH_ (B_ * H_)          // 16 attention batches

// ---------------- scratch ----------------
__device__ float g_q[NR_ * D_];
__device__ float g_k[NR_ * D_];
__device__ float g_v[NR_ * D_];
__device__ float g_attn[NR_ * D_];
__device__ float g_tmp1[NR_ * D_];
__device__ float g_x1[NR_ * D_];
__device__ float g_h1[NR_ * FFN_];
__device__ float g_y[NR_ * D_];

// ================= helpers =================
__device__ __forceinline__ uint32_t pack2(__nv_bfloat16 a, __nv_bfloat16 b) {
    return (uint32_t)__bfloat16_as_ushort(a) | ((uint32_t)__bfloat16_as_ushort(b) << 16);
}
__device__ __forceinline__ void split2(float v, __nv_bfloat16& h, __nv_bfloat16& l) {
    h = __float2bfloat16(v);
    l = __float2bfloat16(v - __bfloat162float(h));
}
__device__ __forceinline__ void mma16816(float* c, const uint32_t* a, const uint32_t* b) {
    asm volatile(
        "mma.sync.aligned.m16n8k16.row.col.f32.bf16.bf16.f32 "
        "{%0,%1,%2,%3}, {%4,%5,%6,%7}, {%8,%9}, {%0,%1,%2,%3};"
        : "+f"(c[0]), "+f"(c[1]), "+f"(c[2]), "+f"(c[3])
        : "r"(a[0]), "r"(a[1]), "r"(a[2]), "r"(a[3]), "r"(b[0]), "r"(b[1]));
}

// ================= flash attention =================
// grid (T/128, BH); 256 threads; 8 warps x 16 Q rows.
// K tiles of 64 keys. Q,K split hi/lo bf16 in smem; V^T split in smem.
// S = scale*(QhKh + QlKh + QhKl); online softmax; O += PhVh + PlVh + PhVl.
#define QP 104          // Q/K smem pitch (elems)
#define VP 72           // V^T smem pitch (elems)
#define SQH 0
#define SQL 13312
#define SKH 26624
#define SKL 33280
#define SVH 39936
#define SVL 46848
#define FLASH_SMEM (53760 * 2)

__global__ __launch_bounds__(256, 1)
void flash_attn(const float* __restrict__ Q,
                const float* __restrict__ Kg,
                const float* __restrict__ Vg,
                float* __restrict__ Og,
                float scale)
{
    extern __shared__ __nv_bfloat16 sm[];
    const int tid = threadIdx.x;
    const int lane = tid & 31;
    const int w = tid >> 5;
    const int rql = lane >> 2;          // 0..7
    const int kof = (lane & 3) << 1;    // 0,2,4,6
    const int q0 = blockIdx.x * 128;
    const int z = blockIdx.y;
    const int bb = z >> 3, hh = z & 7;
    const long base = (long)bb * D_ + (long)hh * HD_;
    const int ldg_row = B_ * D_;        // row stride (t dimension)

    // ---- load Q tile (128 x 96) -> split smem
    {
        const int r = tid >> 1;
        const int c0 = (tid & 1) * 48;
        const float* src = Q + (long)(q0 + r) * ldg_row + base + c0;
        __nv_bfloat16* qh = sm + SQH + r * QP + c0;
        __nv_bfloat16* ql = sm + SQL + r * QP + c0;
#pragma unroll
        for (int j = 0; j < 12; j++) {
            float4 v = *(const float4*)(src + 4 * j);
            __nv_bfloat16 h0,h1,h2,h3,l0,l1,l2,l3;
            split2(v.x,h0,l0); split2(v.y,h1,l1);
            split2(v.z,h2,l2); split2(v.w,h3,l3);
            *(uint2*)(qh + 4*j) = make_uint2(pack2(h0,h1), pack2(h2,h3));
            *(uint2*)(ql + 4*j) = make_uint2(pack2(l0,l1), pack2(l2,l3));
        }
    }
    __syncthreads();

    // ---- Q fragments to registers (rows 16w..16w+15, 6 k-frags)
    uint32_t Qh[6][4], Ql[6][4];
    {
        const int r0 = 16 * w + rql;
#pragma unroll
        for (int kb = 0; kb < 6; kb++) {
            const int kc = kb * 16 + kof;
            Qh[kb][0] = *(const uint32_t*)(sm + SQH + r0 * QP + kc);
            Qh[kb][1] = *(const uint32_t*)(sm + SQH + (r0 + 8) * QP + kc);
            Qh[kb][2] = *(const uint32_t*)(sm + SQH + r0 * QP + kc + 8);
            Qh[kb][3] = *(const uint32_t*)(sm + SQH + (r0 + 8) * QP + kc + 8);
            Ql[kb][0] = *(const uint32_t*)(sm + SQL + r0 * QP + kc);
            Ql[kb][1] = *(const uint32_t*)(sm + SQL + (r0 + 8) * QP + kc);
            Ql[kb][2] = *(const uint32_t*)(sm + SQL + r0 * QP + kc + 8);
            Ql[kb][3] = *(const uint32_t*)(sm + SQL + (r0 + 8) * QP + kc + 8);
        }
    }

    float O[12][4];
#pragma unroll
    for (int i = 0; i < 12; i++)
#pragma unroll
        for (int j = 0; j < 4; j++) O[i][j] = 0.f;
    float mrow[2] = {-1e30f, -1e30f};
    float lrow[2] = {0.f, 0.f};

    for (int s0 = 0; s0 < T_; s0 += 64) {
        __syncthreads();
        // ---- load K tile (64 keys x 96) -> split smem [key][dim]
        {
            const int r = tid >> 2;
            const int c0 = (tid & 3) * 24;
            const float* src = Kg + (long)(s0 + r) * ldg_row + base + c0;
            __nv_bfloat16* kh = sm + SKH + r * QP + c0;
            __nv_bfloat16* kl = sm + SKL + r * QP + c0;
#pragma unroll
            for (int j = 0; j < 6; j++) {
                float4 v = *(const float4*)(src + 4 * j);
                __nv_bfloat16 h0,h1,h2,h3,l0,l1,l2,l3;
                split2(v.x,h0,l0); split2(v.y,h1,l1);
                split2(v.z,h2,l2); split2(v.w,h3,l3);
                *(uint2*)(kh + 4*j) = make_uint2(pack2(h0,h1), pack2(h2,h3));
                *(uint2*)(kl + 4*j) = make_uint2(pack2(l0,l1), pack2(l2,l3));
            }
        }
        // ---- load V tile (64 keys x 96) -> transposed split smem [dim][key]
        {
            const int r = (w & 1) * 32 + lane;
            const int c0 = (w >> 1) * 24;
            const float* src = Vg + (long)(s0 + r) * ldg_row + base + c0;
#pragma unroll
            for (int j = 0; j < 6; j++) {
                float4 v = *(const float4*)(src + 4 * j);
                const float vv[4] = {v.x, v.y, v.z, v.w};
#pragma unroll
                for (int u = 0; u < 4; u++) {
                    __nv_bfloat16 h, l;
                    split2(vv[u], h, l);
                    sm[SVH + (c0 + 4*j + u) * VP + r] = h;
                    sm[SVL + (c0 + 4*j + u) * VP + r] = l;
                }
            }
        }
        __syncthreads();

        // ---- S = scale * Q K^T  (16 x 64 per warp)
        float S[8][4];
#pragma unroll
        for (int nt = 0; nt < 8; nt++) {
            S[nt][0] = S[nt][1] = S[nt][2] = S[nt][3] = 0.f;
            const int n0 = nt * 8 + rql;
#pragma unroll
            for (int kb = 0; kb < 6; kb++) {
                const int kc = kb * 16 + kof;
                uint32_t bh[2], bl[2];
                bh[0] = *(const uint32_t*)(sm + SKH + n0 * QP + kc);
                bh[1] = *(const uint32_t*)(sm + SKH + n0 * QP + kc + 8);
                bl[0] = *(const uint32_t*)(sm + SKL + n0 * QP + kc);
                bl[1] = *(const uint32_t*)(sm + SKL + n0 * QP + kc + 8);
                mma16816(S[nt], Qh[kb], bh);
                mma16816(S[nt], Ql[kb], bh);
                mma16816(S[nt], Qh[kb], bl);
            }
        }

        // ---- online softmax
        float rmax0 = -1e30f, rmax1 = -1e30f;
#pragma unroll
        for (int nt = 0; nt < 8; nt++) {
            S[nt][0] *= scale; S[nt][1] *= scale;
            S[nt][2] *= scale; S[nt][3] *= scale;
            rmax0 = fmaxf(rmax0, fmaxf(S[nt][0], S[nt][1]));
            rmax1 = fmaxf(rmax1, fmaxf(S[nt][2], S[nt][3]));
        }
        rmax0 = fmaxf(rmax0, __shfl_xor_sync(0xffffffffu, rmax0, 1));
        rmax0 = fmaxf(rmax0, __shfl_xor_sync(0xffffffffu, rmax0, 2));
        rmax1 = fmaxf(rmax1, __shfl_xor_sync(0xffffffffu, rmax1, 1));
        rmax1 = fmaxf(rmax1, __shfl_xor_sync(0xffffffffu, rmax1, 2));

        const float m0n = fmaxf(mrow[0], rmax0);
        const float m1n = fmaxf(mrow[1], rmax1);
        const float a0 = __expf(mrow[0] - m0n);
        const float a1 = __expf(mrow[1] - m1n);
        mrow[0] = m0n; mrow[1] = m1n;

        float rs0 = 0.f, rs1 = 0.f;
#pragma unroll
        for (int nt = 0; nt < 8; nt++) {
            S[nt][0] = __expf(S[nt][0] - m0n);
            S[nt][1] = __expf(S[nt][1] - m0n);
            S[nt][2] = __expf(S[nt][2] - m1n);
            S[nt][3] = __expf(S[nt][3] - m1n);
            rs0 += S[nt][0] + S[nt][1];
            rs1 += S[nt][2] + S[nt][3];
        }
        rs0 += __shfl_xor_sync(0xffffffffu, rs0, 1);
        rs0 += __shfl_xor_sync(0xffffffffu, rs0, 2);
        rs1 += __shfl_xor_sync(0xffffffffu, rs1, 1);
        rs1 += __shfl_xor_sync(0xffffffffu, rs1, 2);
        lrow[0] = lrow[0] * a0 + rs0;
        lrow[1] = lrow[1] * a1 + rs1;

#pragma unroll
        for (int i = 0; i < 12; i++) {
            O[i][0] *= a0; O[i][1] *= a0;
            O[i][2] *= a1; O[i][3] *= a1;
        }

        // ---- P -> bf16 hi/lo A-fragments (4 k-frags over 64 keys)
        uint32_t Ph[4][4], Pl[4][4];
#pragma unroll
        for (int kb = 0; kb < 4; kb++) {
            const float* s0f = S[2 * kb];
            const float* s1f = S[2 * kb + 1];
            __nv_bfloat16 h00,h01,h02,h03,h10,h11,h12,h13;
            __nv_bfloat16 l00,l01,l02,l03,l10,l11,l12,l13;
            split2(s0f[0],h00,l00); split2(s0f[1],h01,l01);
            split2(s0f[2],h02,l02); split2(s0f[3],h03,l03);
            split2(s1f[0],h10,l10); split2(s1f[1],h11,l11);
            split2(s1f[2],h12,l12); split2(s1f[3],h13,l13);
            Ph[kb][0] = pack2(h00, h01);
            Ph[kb][1] = pack2(h02, h03);
            Ph[kb][2] = pack2(h10, h11);
            Ph[kb][3] = pack2(h12, h13);
            Pl[kb][0] = pack2(l00, l01);
            Pl[kb][1] = pack2(l02, l03);
            Pl[kb][2] = pack2(l10, l11);
            Pl[kb][3] = pack2(l12, l13);
        }

        // ---- O += P @ V^T  (16 x 96 per warp)
#pragma unroll
        for (int nt = 0; nt < 12; nt++) {
            const int n0 = nt * 8 + rql;
#pragma unroll
            for (int kb = 0; kb < 4; kb++) {
                const int kc = kb * 16 + kof;
                uint32_t bh[2], bl[2];
                bh[0] = *(const uint32_t*)(sm + SVH + n0 * VP + kc);
                bh[1] = *(const uint32_t*)(sm + SVH + n0 * VP + kc + 8);
                bl[0] = *(const uint32_t*)(sm + SVL + n0 * VP + kc);
                bl[1] = *(const uint32_t*)(sm + SVL + n0 * VP + kc + 8);
                mma16816(O[nt], Ph[kb], bh);
                mma16816(O[nt], Pl[kb], bh);
                mma16816(O[nt], Ph[kb], bl);
            }
        }
    }

    // ---- epilogue: O /= l, write out
    const float inv0 = 1.f / lrow[0];
    const float inv1 = 1.f / lrow[1];
    const int r0 = q0 + 16 * w + rql;
#pragma unroll
    for (int nt = 0; nt < 12; nt++) {
        const int cb = nt * 8 + kof;
        float* o0 = Og + (long)r0 * ldg_row + base + cb;
        float* o1 = Og + (long)(r0 + 8) * ldg_row + base + cb;
        *(float2*)o0 = make_float2(O[nt][0] * inv0, O[nt][1] * inv0);
        *(float2*)o1 = make_float2(O[nt][2] * inv1, O[nt][3] * inv1);
    }
}

// ================= HMMA split-bf16 GEMM (dense layers) =================
#define KC 32
#define PA 40
#define TILE_E (128 * PA)
#define GEMM_SMEM (2 * 4 * TILE_E * 2)

__global__ __launch_bounds__(256)
void gemm_hmma(const float* __restrict__ A,
               const float* __restrict__ Bm,
               const float* __restrict__ bias,
               const float* __restrict__ residual,
               float* __restrict__ C,
               int M, int N, int K,
               int lda, int ldb, int ldc,
               float alpha, int relu)
{
    extern __shared__ char dsm[];
    __nv_bfloat16* sm = (__nv_bfloat16*)dsm;

    const int tid = threadIdx.x;
    const int lane = tid & 31;
    const int wid = tid >> 5;
    const int warpM = wid >> 2;
    const int warpN = wid & 3;
    const int rowBase = blockIdx.y * 128;
    const int colBase = blockIdx.x * 128;

    float4 stA[4];
    float4 stB[4];

    auto ldAB = [&](int k0) {
#pragma unroll
        for (int t = 0; t < 4; t++) {
            const int idx = (t << 8) + tid;
            const int r = idx >> 3, kq = (idx & 7) << 2;
            stA[t] = *(const float4*)(A + (long)(rowBase + r) * lda + k0 + kq);
            stB[t] = *(const float4*)(Bm + (long)(colBase + r) * ldb + k0 + kq);
        }
    };
    auto stS = [&](int buf) {
        __nv_bfloat16* pAh = sm + buf * 4 * TILE_E;
        __nv_bfloat16* pAl = pAh + TILE_E;
        __nv_bfloat16* pBh = pAh + 2 * TILE_E;
        __nv_bfloat16* pBl = pAh + 3 * TILE_E;
#pragma unroll
        for (int t = 0; t < 4; t++) {
            const int idx = (t << 8) + tid;
            const int r = idx >> 3, kq = (idx & 7) << 2;
            __nv_bfloat16 h0,h1,h2,h3,l0,l1,l2,l3;
            split2(stA[t].x,h0,l0); split2(stA[t].y,h1,l1);
            split2(stA[t].z,h2,l2); split2(stA[t].w,h3,l3);
            *(uint2*)&pAh[r * PA + kq] = make_uint2(pack2(h0,h1), pack2(h2,h3));
            *(uint2*)&pAl[r * PA + kq] = make_uint2(pack2(l0,l1), pack2(l2,l3));
            split2(stB[t].x,h0,l0); split2(stB[t].y,h1,l1);
            split2(stB[t].z,h2,l2); split2(stB[t].w,h3,l3);
            *(uint2*)&pBh[r * PA + kq] = make_uint2(pack2(h0,h1), pack2(h2,h3));
            *(uint2*)&pBl[r * PA + kq] = make_uint2(pack2(l0,l1), pack2(l2,l3));
        }
    };

    float acc[4][4][4];
#pragma unroll
    for (int i = 0; i < 4; i++)
#pragma unroll
        for (int j = 0; j < 4; j++)
#pragma unroll
            for (int r = 0; r < 4; r++) acc[i][j][r] = 0.f;

    const int NC = K / KC;
    ldAB(0);
    stS(0);
    __syncthreads();

    int buf = 0;
    for (int c = 0; c < NC; c++) {
        const bool has = (c + 1) < NC;
        if (has) ldAB((c + 1) * KC);

        const __nv_bfloat16* pAh = sm + buf * 4 * TILE_E;
        const __nv_bfloat16* pAl = pAh + TILE_E;
        const __nv_bfloat16* pBh = pAh + 2 * TILE_E;
        const __nv_bfloat16* pBl = pAh + 3 * TILE_E;
        const int rql = lane >> 2;
        const int kof = (lane & 3) << 1;

#pragma unroll
        for (int ks = 0; ks < KC; ks += 16) {
            const int kcol = ks + kof;
            uint32_t bh[4][2], bl[4][2];
#pragma unroll
            for (int nt = 0; nt < 4; nt++) {
                const int n0 = warpN * 32 + nt * 8 + rql;
                bh[nt][0] = *(const uint32_t*)&pBh[n0 * PA + kcol];
                bh[nt][1] = *(const uint32_t*)&pBh[n0 * PA + kcol + 8];
                bl[nt][0] = *(const uint32_t*)&pBl[n0 * PA + kcol];
                bl[nt][1] = *(const uint32_t*)&pBl[n0 * PA + kcol + 8];
            }
#pragma unroll
            for (int mt = 0; mt < 4; mt++) {
                const int r0 = warpM * 64 + mt * 16 + rql;
                uint32_t ah[4], al[4];
                ah[0] = *(const uint32_t*)&pAh[r0 * PA + kcol];
                ah[1] = *(const uint32_t*)&pAh[(r0 + 8) * PA + kcol];
                ah[2] = *(const uint32_t*)&pAh[r0 * PA + kcol + 8];
                ah[3] = *(const uint32_t*)&pAh[(r0 + 8) * PA + kcol + 8];
                al[0] = *(const uint32_t*)&pAl[r0 * PA + kcol];
                al[1] = *(const uint32_t*)&pAl[(r0 + 8) * PA + kcol];
                al[2] = *(const uint32_t*)&pAl[r0 * PA + kcol + 8];
                al[3] = *(const uint32_t*)&pAl[(r0 + 8) * PA + kcol + 8];
#pragma unroll
                for (int nt = 0; nt < 4; nt++) {
                    mma16816(acc[mt][nt], ah, bh[nt]);
                    mma16816(acc[mt][nt], ah, bl[nt]);
                    mma16816(acc[mt][nt], al, bh[nt]);
                }
            }
        }

        if (has) stS(buf ^ 1);
        __syncthreads();
        buf ^= 1;
    }

    const int rql = lane >> 2;
    const int cof = (lane & 3) << 1;
#pragma unroll
    for (int mt = 0; mt < 4; mt++) {
        const int r0 = rowBase + warpM * 64 + mt * 16 + rql;
#pragma unroll
        for (int nt = 0; nt < 4; nt++) {
            const int cb = colBase + warpN * 32 + nt * 8 + cof;
            float* a4 = acc[mt][nt];
            float2 bb = make_float2(0.f, 0.f);
            if (bias) bb = *(const float2*)(bias + cb);
            float v0 = a4[0] * alpha + bb.x;
            float v1 = a4[1] * alpha + bb.y;
            float v2 = a4[2] * alpha + bb.x;
            float v3 = a4[3] * alpha + bb.y;
            if (relu) {
                v0 = fmaxf(v0, 0.f); v1 = fmaxf(v1, 0.f);
                v2 = fmaxf(v2, 0.f); v3 = fmaxf(v3, 0.f);
            }
            const long o0 = (long)r0 * ldc + cb;
            const long o1 = (long)(r0 + 8) * ldc + cb;
            if (residual) {
                float2 r00 = *(const float2*)(residual + o0);
                float2 r11 = *(const float2*)(residual + o1);
                v0 += r00.x; v1 += r00.y; v2 += r11.x; v3 += r11.y;
            }
            *(float2*)(C + o0) = make_float2(v0, v1);
            *(float2*)(C + o1) = make_float2(v2, v3);
        }
    }
}

// ---------------- block reductions ----------------
__device__ __forceinline__ float blockReduceSum(float v) {
    __shared__ float s[8];
#pragma unroll
    for (int o = 16; o > 0; o >>= 1) v += __shfl_xor_sync(0xffffffffu, v, o);
    int w = threadIdx.x >> 5, l = threadIdx.x & 31;
    if (l == 0) s[w] = v;
    __syncthreads();
    if (threadIdx.x < 32) {
        v = (threadIdx.x < 8) ? s[threadIdx.x] : 0.f;
#pragma unroll
        for (int o = 4; o > 0; o >>= 1) v += __shfl_xor_sync(0xffffffffu, v, o);
        if (threadIdx.x == 0) s[0] = v;
    }
    __syncthreads();
    v = s[0];
    __syncthreads();
    return v;
}

// ---------------- layernorm over rows of length 768 ----------------
__global__ void layernorm_kernel(const float* __restrict__ X,
                                 const float* __restrict__ g,
                                 const float* __restrict__ b,
                                 float* __restrict__ Y) {
    long row = blockIdx.x;
    const float* p = X + row * D_;
    float* q = Y + row * D_;
    int tid = threadIdx.x;
    float vals[3];
    float sum = 0.f;
#pragma unroll
    for (int i = 0; i < 3; i++) {
        vals[i] = p[tid + i * 256];
        sum += vals[i];
    }
    float mu = blockReduceSum(sum) * (1.f / D_);
    float vs = 0.f;
#pragma unroll
    for (int i = 0; i < 3; i++) {
        float d = vals[i] - mu;
        vs += d * d;
    }
    float var = blockReduceSum(vs) * (1.f / D_);
    float rs = rsqrtf(var + 1e-5f);
#pragma unroll
    for (int i = 0; i < 3; i++) {
        int c = tid + i * 256;
        q[c] = (vals[i] - mu) * rs * g[c] + b[c];
    }
}

// ---------------- launch ----------------
extern "C" void kernel_launch(void* const* d_in, const int* in_sizes, int n_in,
                              void* d_out, int out_size)
{
    const float* x     = (const float*)d_in[0];
    const float* wq    = (const float*)d_in[1];
    const float* bq    = (const float*)d_in[2];
    const float* wk    = (const float*)d_in[3];
    const float* bk    = (const float*)d_in[4];
    const float* wv    = (const float*)d_in[5];
    const float* bv    = (const float*)d_in[6];
    const float* wo    = (const float*)d_in[7];
    const float* bo    = (const float*)d_in[8];
    const float* ln1g  = (const float*)d_in[9];
    const float* ln1b  = (const float*)d_in[10];
    const float* w1    = (const float*)d_in[11];
    const float* b1    = (const float*)d_in[12];
    const float* w2    = (const float*)d_in[13];
    const float* b2    = (const float*)d_in[14];
    const float* ln2g  = (const float*)d_in[15];
    const float* ln2b  = (const float*)d_in[16];
    float* out = (float*)d_out;

    float *q, *k, *v, *attn, *tmp1, *x1, *h1, *y;
    cudaGetSymbolAddress((void**)&q,    g_q);
    cudaGetSymbolAddress((void**)&k,    g_k);
    cudaGetSymbolAddress((void**)&v,    g_v);
    cudaGetSymbolAddress((void**)&attn, g_attn);
    cudaGetSymbolAddress((void**)&tmp1, g_tmp1);
    cudaGetSymbolAddress((void**)&x1,   g_x1);
    cudaGetSymbolAddress((void**)&h1,   g_h1);
    cudaGetSymbolAddress((void**)&y,    g_y);

    cudaFuncSetAttribute(gemm_hmma, cudaFuncAttributeMaxDynamicSharedMemorySize, GEMM_SMEM);
    cudaFuncSetAttribute(flash_attn, cudaFuncAttributeMaxDynamicSharedMemorySize, FLASH_SMEM);

    const float scale = 0.102062072615966f;  // 1/sqrt(96)
    dim3 blk(256);

    // QKV projections
    dim3 gProj(D_ / 128, NR_ / 128);
    gemm_hmma<<<gProj, blk, GEMM_SMEM>>>(x, wq, bq, nullptr, q, NR_, D_, D_,
                                         D_, D_, D_, 1.f, 0);
    gemm_hmma<<<gProj, blk, GEMM_SMEM>>>(x, wk, bk, nullptr, k, NR_, D_, D_,
                                         D_, D_, D_, 1.f, 0);
    gemm_hmma<<<gProj, blk, GEMM_SMEM>>>(x, wv, bv, nullptr, v, NR_, D_, D_,
                                         D_, D_, D_, 1.f, 0);

    // fused flash attention
    dim3 gFA(T_ / 128, BH_);
    flash_attn<<<gFA, blk, FLASH_SMEM>>>(q, k, v, attn, scale);

    // O projection + residual(x)
    gemm_hmma<<<gProj, blk, GEMM_SMEM>>>(attn, wo, bo, x, tmp1, NR_, D_, D_,
                                         D_, D_, D_, 1.f, 0);

    layernorm_kernel<<<NR_, blk>>>(tmp1, ln1g, ln1b, x1);

    // FFN1: relu(x1 @ w1^T + b1)
    dim3 gF1(FFN_ / 128, NR_ / 128);
    gemm_hmma<<<gF1, blk, GEMM_SMEM>>>(x1, w1, b1, nullptr, h1, NR_, FFN_, D_,
                                       D_, D_, FFN_, 1.f, 1);

    // FFN2: h1 @ w2^T + b2 + x1
    gemm_hmma<<<gProj, blk, GEMM_SMEM>>>(h1, w2, b2, x1, y, NR_, D_, FFN_,
                                         FFN_, FFN_, D_, 1.f, 0);

    layernorm_kernel<<<NR_, blk>>>(y, ln2g, ln2b, out);
}

// round 8
// speedup vs baseline: 3.3345x; 1.0337x over previous
#include <cuda_runtime.h>
#include <cuda_bf16.h>
#include <math.h>
#include <stdint.h>

// Problem constants
#define T_ 2048
#define B_ 2
#define D_ 768
#define H_ 8
#define HD_ 96
#define FFN_ 3072
#define NR_ (T_ * B_)          // 4096 rows
#define BH_ (B_ * H_)          // 16 attention batches

// ---------------- scratch ----------------
__device__ float g_q[NR_ * D_];
__device__ float g_k[NR_ * D_];
__device__ float g_v[NR_ * D_];
__device__ float g_attn[NR_ * D_];
__device__ float g_tmp1[NR_ * D_];
__device__ float g_x1[NR_ * D_];
__device__ float g_h1[NR_ * FFN_];
__device__ float g_y[NR_ * D_];

// ================= helpers =================
__device__ __forceinline__ uint32_t pack2(__nv_bfloat16 a, __nv_bfloat16 b) {
    return (uint32_t)__bfloat16_as_ushort(a) | ((uint32_t)__bfloat16_as_ushort(b) << 16);
}
__device__ __forceinline__ void split2(float v, __nv_bfloat16& h, __nv_bfloat16& l) {
    h = __float2bfloat16(v);
    l = __float2bfloat16(v - __bfloat162float(h));
}
__device__ __forceinline__ void mma16816(float* c, const uint32_t* a, const uint32_t* b) {
    asm volatile(
        "mma.sync.aligned.m16n8k16.row.col.f32.bf16.bf16.f32 "
        "{%0,%1,%2,%3}, {%4,%5,%6,%7}, {%8,%9}, {%0,%1,%2,%3};"
        : "+f"(c[0]), "+f"(c[1]), "+f"(c[2]), "+f"(c[3])
        : "r"(a[0]), "r"(a[1]), "r"(a[2]), "r"(a[3]), "r"(b[0]), "r"(b[1]));
}

// ================= flash attention =================
// grid (T/64, BH); 128 threads; 4 warps x 16 Q rows (64 rows per CTA).
// 2 CTAs co-resident per SM -> cross-CTA latency hiding.
// K tiles of 64 keys. Q,K split hi/lo bf16 in smem; V^T split in smem.
// S2 = scale*log2e*(QhKh + QlKh + QhKl); online softmax in base-2; O += PhVh + PlVh + PhVl.
#define QP 104          // Q/K smem pitch (elems)
#define VP 72           // V^T smem pitch (elems)
#define SQH 0
#define SQL 6656
#define SKH 13312
#define SKL 19968
#define SVH 26624
#define SVL 33536
#define FLASH_SMEM (40448 * 2)

__global__ __launch_bounds__(128, 2)
void flash_attn(const float* __restrict__ Q,
                const float* __restrict__ Kg,
                const float* __restrict__ Vg,
                float* __restrict__ Og,
                float scale2)   // scale * log2(e)
{
    extern __shared__ __nv_bfloat16 sm[];
    const int tid = threadIdx.x;
    const int lane = tid & 31;
    const int w = tid >> 5;             // 0..3
    const int rql = lane >> 2;          // 0..7
    const int kof = (lane & 3) << 1;    // 0,2,4,6
    const int q0 = blockIdx.x * 64;
    const int z = blockIdx.y;
    const int bb = z >> 3, hh = z & 7;
    const long base = (long)bb * D_ + (long)hh * HD_;
    const int ldg_row = B_ * D_;        // row stride (t dimension)

    // ---- load Q tile (64 x 96) -> split smem
    {
        const int r = tid >> 1;
        const int c0 = (tid & 1) * 48;
        const float* src = Q + (long)(q0 + r) * ldg_row + base + c0;
        __nv_bfloat16* qh = sm + SQH + r * QP + c0;
        __nv_bfloat16* ql = sm + SQL + r * QP + c0;
#pragma unroll
        for (int j = 0; j < 12; j++) {
            float4 v = *(const float4*)(src + 4 * j);
            __nv_bfloat16 h0,h1,h2,h3,l0,l1,l2,l3;
            split2(v.x,h0,l0); split2(v.y,h1,l1);
            split2(v.z,h2,l2); split2(v.w,h3,l3);
            *(uint2*)(qh + 4*j) = make_uint2(pack2(h0,h1), pack2(h2,h3));
            *(uint2*)(ql + 4*j) = make_uint2(pack2(l0,l1), pack2(l2,l3));
        }
    }
    __syncthreads();

    // ---- Q fragments to registers (rows 16w..16w+15, 6 k-frags)
    uint32_t Qh[6][4], Ql[6][4];
    {
        const int r0 = 16 * w + rql;
#pragma unroll
        for (int kb = 0; kb < 6; kb++) {
            const int kc = kb * 16 + kof;
            Qh[kb][0] = *(const uint32_t*)(sm + SQH + r0 * QP + kc);
            Qh[kb][1] = *(const uint32_t*)(sm + SQH + (r0 + 8) * QP + kc);
            Qh[kb][2] = *(const uint32_t*)(sm + SQH + r0 * QP + kc + 8);
            Qh[kb][3] = *(const uint32_t*)(sm + SQH + (r0 + 8) * QP + kc + 8);
            Ql[kb][0] = *(const uint32_t*)(sm + SQL + r0 * QP + kc);
            Ql[kb][1] = *(const uint32_t*)(sm + SQL + (r0 + 8) * QP + kc);
            Ql[kb][2] = *(const uint32_t*)(sm + SQL + r0 * QP + kc + 8);
            Ql[kb][3] = *(const uint32_t*)(sm + SQL + (r0 + 8) * QP + kc + 8);
        }
    }

    float O[12][4];
#pragma unroll
    for (int i = 0; i < 12; i++)
#pragma unroll
        for (int j = 0; j < 4; j++) O[i][j] = 0.f;
    float mrow[2] = {-1e30f, -1e30f};
    float lrow[2] = {0.f, 0.f};

    for (int s0 = 0; s0 < T_; s0 += 64) {
        __syncthreads();
        // ---- load K tile (64 keys x 96) -> split smem [key][dim]
        {
            const int r = tid >> 1;
            const int c0 = (tid & 1) * 48;
            const float* src = Kg + (long)(s0 + r) * ldg_row + base + c0;
            __nv_bfloat16* kh = sm + SKH + r * QP + c0;
            __nv_bfloat16* kl = sm + SKL + r * QP + c0;
#pragma unroll
            for (int j = 0; j < 12; j++) {
                float4 v = *(const float4*)(src + 4 * j);
                __nv_bfloat16 h0,h1,h2,h3,l0,l1,l2,l3;
                split2(v.x,h0,l0); split2(v.y,h1,l1);
                split2(v.z,h2,l2); split2(v.w,h3,l3);
                *(uint2*)(kh + 4*j) = make_uint2(pack2(h0,h1), pack2(h2,h3));
                *(uint2*)(kl + 4*j) = make_uint2(pack2(l0,l1), pack2(l2,l3));
            }
        }
        // ---- load V tile (64 keys x 96) -> transposed split smem [dim][key]
        {
            const int r = (w & 1) * 32 + lane;
            const int c0 = (w >> 1) * 48;
            const float* src = Vg + (long)(s0 + r) * ldg_row + base + c0;
#pragma unroll
            for (int j = 0; j < 12; j++) {
                float4 v = *(const float4*)(src + 4 * j);
                const float vv[4] = {v.x, v.y, v.z, v.w};
#pragma unroll
                for (int u = 0; u < 4; u++) {
                    __nv_bfloat16 h, l;
                    split2(vv[u], h, l);
                    sm[SVH + (c0 + 4*j + u) * VP + r] = h;
                    sm[SVL + (c0 + 4*j + u) * VP + r] = l;
                }
            }
        }
        __syncthreads();

        // ---- S = Q K^T  (16 x 64 per warp)
        float S[8][4];
#pragma unroll
        for (int nt = 0; nt < 8; nt++) {
            S[nt][0] = S[nt][1] = S[nt][2] = S[nt][3] = 0.f;
            const int n0 = nt * 8 + rql;
#pragma unroll
            for (int kb = 0; kb < 6; kb++) {
                const int kc = kb * 16 + kof;
                uint32_t bh[2], bl[2];
                bh[0] = *(const uint32_t*)(sm + SKH + n0 * QP + kc);
                bh[1] = *(const uint32_t*)(sm + SKH + n0 * QP + kc + 8);
                bl[0] = *(const uint32_t*)(sm + SKL + n0 * QP + kc);
                bl[1] = *(const uint32_t*)(sm + SKL + n0 * QP + kc + 8);
                mma16816(S[nt], Qh[kb], bh);
                mma16816(S[nt], Ql[kb], bh);
                mma16816(S[nt], Qh[kb], bl);
            }
        }

        // ---- online softmax (base-2 domain)
        float rmax0 = -1e30f, rmax1 = -1e30f;
#pragma unroll
        for (int nt = 0; nt < 8; nt++) {
            S[nt][0] *= scale2; S[nt][1] *= scale2;
            S[nt][2] *= scale2; S[nt][3] *= scale2;
            rmax0 = fmaxf(rmax0, fmaxf(S[nt][0], S[nt][1]));
            rmax1 = fmaxf(rmax1, fmaxf(S[nt][2], S[nt][3]));
        }
        rmax0 = fmaxf(rmax0, __shfl_xor_sync(0xffffffffu, rmax0, 1));
        rmax0 = fmaxf(rmax0, __shfl_xor_sync(0xffffffffu, rmax0, 2));
        rmax1 = fmaxf(rmax1, __shfl_xor_sync(0xffffffffu, rmax1, 1));
        rmax1 = fmaxf(rmax1, __shfl_xor_sync(0xffffffffu, rmax1, 2));

        const float m0n = fmaxf(mrow[0], rmax0);
        const float m1n = fmaxf(mrow[1], rmax1);
        const float a0 = exp2f(mrow[0] - m0n);
        const float a1 = exp2f(mrow[1] - m1n);
        mrow[0] = m0n; mrow[1] = m1n;

        float rs0 = 0.f, rs1 = 0.f;
#pragma unroll
        for (int nt = 0; nt < 8; nt++) {
            S[nt][0] = exp2f(S[nt][0] - m0n);
            S[nt][1] = exp2f(S[nt][1] - m0n);
            S[nt][2] = exp2f(S[nt][2] - m1n);
            S[nt][3] = exp2f(S[nt][3] - m1n);
            rs0 += S[nt][0] + S[nt][1];
            rs1 += S[nt][2] + S[nt][3];
        }
        rs0 += __shfl_xor_sync(0xffffffffu, rs0, 1);
        rs0 += __shfl_xor_sync(0xffffffffu, rs0, 2);
        rs1 += __shfl_xor_sync(0xffffffffu, rs1, 1);
        rs1 += __shfl_xor_sync(0xffffffffu, rs1, 2);
        lrow[0] = lrow[0] * a0 + rs0;
        lrow[1] = lrow[1] * a1 + rs1;

#pragma unroll
        for (int i = 0; i < 12; i++) {
            O[i][0] *= a0; O[i][1] *= a0;
            O[i][2] *= a1; O[i][3] *= a1;
        }

        // ---- P -> bf16 hi/lo A-fragments (4 k-frags over 64 keys)
        uint32_t Ph[4][4], Pl[4][4];
#pragma unroll
        for (int kb = 0; kb < 4; kb++) {
            const float* s0f = S[2 * kb];
            const float* s1f = S[2 * kb + 1];
            __nv_bfloat16 h00,h01,h02,h03,h10,h11,h12,h13;
            __nv_bfloat16 l00,l01,l02,l03,l10,l11,l12,l13;
            split2(s0f[0],h00,l00); split2(s0f[1],h01,l01);
            split2(s0f[2],h02,l02); split2(s0f[3],h03,l03);
            split2(s1f[0],h10,l10); split2(s1f[1],h11,l11);
            split2(s1f[2],h12,l12); split2(s1f[3],h13,l13);
            Ph[kb][0] = pack2(h00, h01);
            Ph[kb][1] = pack2(h02, h03);
            Ph[kb][2] = pack2(h10, h11);
            Ph[kb][3] = pack2(h12, h13);
            Pl[kb][0] = pack2(l00, l01);
            Pl[kb][1] = pack2(l02, l03);
            Pl[kb][2] = pack2(l10, l11);
            Pl[kb][3] = pack2(l12, l13);
        }

        // ---- O += P @ V^T  (16 x 96 per warp)
#pragma unroll
        for (int nt = 0; nt < 12; nt++) {
            const int n0 = nt * 8 + rql;
#pragma unroll
            for (int kb = 0; kb < 4; kb++) {
                const int kc = kb * 16 + kof;
                uint32_t bh[2], bl[2];
                bh[0] = *(const uint32_t*)(sm + SVH + n0 * VP + kc);
                bh[1] = *(const uint32_t*)(sm + SVH + n0 * VP + kc + 8);
                bl[0] = *(const uint32_t*)(sm + SVL + n0 * VP + kc);
                bl[1] = *(const uint32_t*)(sm + SVL + n0 * VP + kc + 8);
                mma16816(O[nt], Ph[kb], bh);
                mma16816(O[nt], Pl[kb], bh);
                mma16816(O[nt], Ph[kb], bl);
            }
        }
    }

    // ---- epilogue: O /= l, write out
    const float inv0 = 1.f / lrow[0];
    const float inv1 = 1.f / lrow[1];
    const int r0 = q0 + 16 * w + rql;
#pragma unroll
    for (int nt = 0; nt < 12; nt++) {
        const int cb = nt * 8 + kof;
        float* o0 = Og + (long)r0 * ldg_row + base + cb;
        float* o1 = Og + (long)(r0 + 8) * ldg_row + base + cb;
        *(float2*)o0 = make_float2(O[nt][0] * inv0, O[nt][1] * inv0);
        *(float2*)o1 = make_float2(O[nt][2] * inv1, O[nt][3] * inv1);
    }
}

// ================= HMMA split-bf16 GEMM body (dense layers) =================
#define KC 32
#define PA 40
#define TILE_E (128 * PA)
#define GEMM_SMEM (2 * 4 * TILE_E * 2)

__device__ __forceinline__
void gemm_body(__nv_bfloat16* sm,
               const float* __restrict__ A,
               const float* __restrict__ Bm,
               const float* __restrict__ bias,
               const float* __restrict__ residual,
               float* __restrict__ C,
               int K, int lda, int ldb, int ldc, int relu)
{
    const int tid = threadIdx.x;
    const int lane = tid & 31;
    const int wid = tid >> 5;
    const int warpM = wid >> 2;
    const int warpN = wid & 3;
    const int rowBase = blockIdx.y * 128;
    const int colBase = blockIdx.x * 128;

    float4 stA[4];
    float4 stB[4];

    auto ldAB = [&](int k0) {
#pragma unroll
        for (int t = 0; t < 4; t++) {
            const int idx = (t << 8) + tid;
            const int r = idx >> 3, kq = (idx & 7) << 2;
            stA[t] = *(const float4*)(A + (long)(rowBase + r) * lda + k0 + kq);
            stB[t] = *(const float4*)(Bm + (long)(colBase + r) * ldb + k0 + kq);
        }
    };
    auto stS = [&](int buf) {
        __nv_bfloat16* pAh = sm + buf * 4 * TILE_E;
        __nv_bfloat16* pAl = pAh + TILE_E;
        __nv_bfloat16* pBh = pAh + 2 * TILE_E;
        __nv_bfloat16* pBl = pAh + 3 * TILE_E;
#pragma unroll
        for (int t = 0; t < 4; t++) {
            const int idx = (t << 8) + tid;
            const int r = idx >> 3, kq = (idx & 7) << 2;
            __nv_bfloat16 h0,h1,h2,h3,l0,l1,l2,l3;
            split2(stA[t].x,h0,l0); split2(stA[t].y,h1,l1);
            split2(stA[t].z,h2,l2); split2(stA[t].w,h3,l3);
            *(uint2*)&pAh[r * PA + kq] = make_uint2(pack2(h0,h1), pack2(h2,h3));
            *(uint2*)&pAl[r * PA + kq] = make_uint2(pack2(l0,l1), pack2(l2,l3));
            split2(stB[t].x,h0,l0); split2(stB[t].y,h1,l1);
            split2(stB[t].z,h2,l2); split2(stB[t].w,h3,l3);
            *(uint2*)&pBh[r * PA + kq] = make_uint2(pack2(h0,h1), pack2(h2,h3));
            *(uint2*)&pBl[r * PA + kq] = make_uint2(pack2(l0,l1), pack2(l2,l3));
        }
    };

    float acc[4][4][4];
#pragma unroll
    for (int i = 0; i < 4; i++)
#pragma unroll
        for (int j = 0; j < 4; j++)
#pragma unroll
            for (int r = 0; r < 4; r++) acc[i][j][r] = 0.f;

    const int NC = K / KC;
    ldAB(0);
    stS(0);
    __syncthreads();

    int buf = 0;
    for (int c = 0; c < NC; c++) {
        const bool has = (c + 1) < NC;
        if (has) ldAB((c + 1) * KC);

        const __nv_bfloat16* pAh = sm + buf * 4 * TILE_E;
        const __nv_bfloat16* pAl = pAh + TILE_E;
        const __nv_bfloat16* pBh = pAh + 2 * TILE_E;
        const __nv_bfloat16* pBl = pAh + 3 * TILE_E;
        const int rql = lane >> 2;
        const int kof = (lane & 3) << 1;

#pragma unroll
        for (int ks = 0; ks < KC; ks += 16) {
            const int kcol = ks + kof;
            uint32_t bh[4][2], bl[4][2];
#pragma unroll
            for (int nt = 0; nt < 4; nt++) {
                const int n0 = warpN * 32 + nt * 8 + rql;
                bh[nt][0] = *(const uint32_t*)&pBh[n0 * PA + kcol];
                bh[nt][1] = *(const uint32_t*)&pBh[n0 * PA + kcol + 8];
                bl[nt][0] = *(const uint32_t*)&pBl[n0 * PA + kcol];
                bl[nt][1] = *(const uint32_t*)&pBl[n0 * PA + kcol + 8];
            }
#pragma unroll
            for (int mt = 0; mt < 4; mt++) {
                const int r0 = warpM * 64 + mt * 16 + rql;
                uint32_t ah[4], al[4];
                ah[0] = *(const uint32_t*)&pAh[r0 * PA + kcol];
                ah[1] = *(const uint32_t*)&pAh[(r0 + 8) * PA + kcol];
                ah[2] = *(const uint32_t*)&pAh[r0 * PA + kcol + 8];
                ah[3] = *(const uint32_t*)&pAh[(r0 + 8) * PA + kcol + 8];
                al[0] = *(const uint32_t*)&pAl[r0 * PA + kcol];
                al[1] = *(const uint32_t*)&pAl[(r0 + 8) * PA + kcol];
                al[2] = *(const uint32_t*)&pAl[r0 * PA + kcol + 8];
                al[3] = *(const uint32_t*)&pAl[(r0 + 8) * PA + kcol + 8];
#pragma unroll
                for (int nt = 0; nt < 4; nt++) {
                    mma16816(acc[mt][nt], ah, bh[nt]);
                    mma16816(acc[mt][nt], ah, bl[nt]);
                    mma16816(acc[mt][nt], al, bh[nt]);
                }
            }
        }

        if (has) stS(buf ^ 1);
        __syncthreads();
        buf ^= 1;
    }

    const int rql = lane >> 2;
    const int cof = (lane & 3) << 1;
#pragma unroll
    for (int mt = 0; mt < 4; mt++) {
        const int r0 = rowBase + warpM * 64 + mt * 16 + rql;
#pragma unroll
        for (int nt = 0; nt < 4; nt++) {
            const int cb = colBase + warpN * 32 + nt * 8 + cof;
            float* a4 = acc[mt][nt];
            float2 bb = make_float2(0.f, 0.f);
            if (bias) bb = *(const float2*)(bias + cb);
            float v0 = a4[0] + bb.x;
            float v1 = a4[1] + bb.y;
            float v2 = a4[2] + bb.x;
            float v3 = a4[3] + bb.y;
            if (relu) {
                v0 = fmaxf(v0, 0.f); v1 = fmaxf(v1, 0.f);
                v2 = fmaxf(v2, 0.f); v3 = fmaxf(v3, 0.f);
            }
            const long o0 = (long)r0 * ldc + cb;
            const long o1 = (long)(r0 + 8) * ldc + cb;
            if (residual) {
                float2 r00 = *(const float2*)(residual + o0);
                float2 r11 = *(const float2*)(residual + o1);
                v0 += r00.x; v1 += r00.y; v2 += r11.x; v3 += r11.y;
            }
            *(float2*)(C + o0) = make_float2(v0, v1);
            *(float2*)(C + o1) = make_float2(v2, v3);
        }
    }
}

__global__ __launch_bounds__(256)
void gemm_hmma(const float* __restrict__ A,
               const float* __restrict__ Bm,
               const float* __restrict__ bias,
               const float* __restrict__ residual,
               float* __restrict__ C,
               int K, int lda, int ldb, int ldc, int relu)
{
    extern __shared__ char dsm[];
    gemm_body((__nv_bfloat16*)dsm, A, Bm, bias, residual, C, K, lda, ldb, ldc, relu);
}

// fused QKV: blockIdx.z selects weight/bias/output
__global__ __launch_bounds__(256)
void gemm_qkv(const float* __restrict__ A,
              const float* __restrict__ w0, const float* __restrict__ w1,
              const float* __restrict__ w2,
              const float* __restrict__ b0, const float* __restrict__ b1,
              const float* __restrict__ b2,
              float* __restrict__ c0, float* __restrict__ c1,
              float* __restrict__ c2)
{
    extern __shared__ char dsm[];
    const int z = blockIdx.z;
    const float* Bm = (z == 0) ? w0 : (z == 1) ? w1 : w2;
    const float* bias = (z == 0) ? b0 : (z == 1) ? b1 : b2;
    float* C = (z == 0) ? c0 : (z == 1) ? c1 : c2;
    gemm_body((__nv_bfloat16*)dsm, A, Bm, bias, nullptr, C, D_, D_, D_, D_, 0);
}

// ---------------- block reduction ----------------
__device__ __forceinline__ float blockReduceSum(float v) {
    __shared__ float s[8];
#pragma unroll
    for (int o = 16; o > 0; o >>= 1) v += __shfl_xor_sync(0xffffffffu, v, o);
    int w = threadIdx.x >> 5, l = threadIdx.x & 31;
    if (l == 0) s[w] = v;
    __syncthreads();
    if (threadIdx.x < 32) {
        v = (threadIdx.x < 8) ? s[threadIdx.x] : 0.f;
#pragma unroll
        for (int o = 4; o > 0; o >>= 1) v += __shfl_xor_sync(0xffffffffu, v, o);
        if (threadIdx.x == 0) s[0] = v;
    }
    __syncthreads();
    v = s[0];
    __syncthreads();
    return v;
}

// ---------------- layernorm over rows of length 768 ----------------
__global__ void layernorm_kernel(const float* __restrict__ X,
                                 const float* __restrict__ g,
                                 const float* __restrict__ b,
                                 float* __restrict__ Y) {
    long row = blockIdx.x;
    const float* p = X + row * D_;
    float* q = Y + row * D_;
    int tid = threadIdx.x;
    float vals[3];
    float sum = 0.f;
#pragma unroll
    for (int i = 0; i < 3; i++) {
        vals[i] = p[tid + i * 256];
        sum += vals[i];
    }
    float mu = blockReduceSum(sum) * (1.f / D_);
    float vs = 0.f;
#pragma unroll
    for (int i = 0; i < 3; i++) {
        float d = vals[i] - mu;
        vs += d * d;
    }
    float var = blockReduceSum(vs) * (1.f / D_);
    float rs = rsqrtf(var + 1e-5f);
#pragma unroll
    for (int i = 0; i < 3; i++) {
        int c = tid + i * 256;
        q[c] = (vals[i] - mu) * rs * g[c] + b[c];
    }
}

// ---------------- launch ----------------
extern "C" void kernel_launch(void* const* d_in, const int* in_sizes, int n_in,
                              void* d_out, int out_size)
{
    const float* x     = (const float*)d_in[0];
    const float* wq    = (const float*)d_in[1];
    const float* bq    = (const float*)d_in[2];
    const float* wk    = (const float*)d_in[3];
    const float* bk    = (const float*)d_in[4];
    const float* wv    = (const float*)d_in[5];
    const float* bv    = (const float*)d_in[6];
    const float* wo    = (const float*)d_in[7];
    const float* bo    = (const float*)d_in[8];
    const float* ln1g  = (const float*)d_in[9];
    const float* ln1b  = (const float*)d_in[10];
    const float* w1    = (const float*)d_in[11];
    const float* b1    = (const float*)d_in[12];
    const float* w2    = (const float*)d_in[13];
    const float* b2    = (const float*)d_in[14];
    const float* ln2g  = (const float*)d_in[15];
    const float* ln2b  = (const float*)d_in[16];
    float* out = (float*)d_out;

    float *q, *k, *v, *attn, *tmp1, *x1, *h1, *y;
    cudaGetSymbolAddress((void**)&q,    g_q);
    cudaGetSymbolAddress((void**)&k,    g_k);
    cudaGetSymbolAddress((void**)&v,    g_v);
    cudaGetSymbolAddress((void**)&attn, g_attn);
    cudaGetSymbolAddress((void**)&tmp1, g_tmp1);
    cudaGetSymbolAddress((void**)&x1,   g_x1);
    cudaGetSymbolAddress((void**)&h1,   g_h1);
    cudaGetSymbolAddress((void**)&y,    g_y);

    cudaFuncSetAttribute(gemm_hmma, cudaFuncAttributeMaxDynamicSharedMemorySize, GEMM_SMEM);
    cudaFuncSetAttribute(gemm_qkv,  cudaFuncAttributeMaxDynamicSharedMemorySize, GEMM_SMEM);
    cudaFuncSetAttribute(flash_attn, cudaFuncAttributeMaxDynamicSharedMemorySize, FLASH_SMEM);

    const float scale2 = 0.102062072615966f * 1.44269504088896f;  // 1/sqrt(96)*log2(e)
    dim3 blk(256);

    // QKV projections (fused launch; z selects q/k/v)
    dim3 gQKV(D_ / 128, NR_ / 128, 3);
    gemm_qkv<<<gQKV, blk, GEMM_SMEM>>>(x, wq, wk, wv, bq, bk, bv, q, k, v);

    // fused flash attention
    dim3 gFA(T_ / 64, BH_);
    flash_attn<<<gFA, dim3(128), FLASH_SMEM>>>(q, k, v, attn, scale2);

    // O projection + residual(x)
    dim3 gProj(D_ / 128, NR_ / 128);
    gemm_hmma<<<gProj, blk, GEMM_SMEM>>>(attn, wo, bo, x, tmp1, D_, D_, D_, D_, 0);

    layernorm_kernel<<<NR_, blk>>>(tmp1, ln1g, ln1b, x1);

    // FFN1: relu(x1 @ w1^T + b1)
    dim3 gF1(FFN_ / 128, NR_ / 128);
    gemm_hmma<<<gF1, blk, GEMM_SMEM>>>(x1, w1, b1, nullptr, h1, D_, D_, D_, FFN_, 1);

    // FFN2: h1 @ w2^T + b2 + x1
    gemm_hmma<<<gProj, blk, GEMM_SMEM>>>(h1, w2, b2, x1, y, FFN_, FFN_, FFN_, D_, 0);

    layernorm_kernel<<<NR_, blk>>>(y, ln2g, ln2b, out);
}